// round 2
// baseline (speedup 1.0000x reference)
#include <cuda_runtime.h>
#include <cstdint>

// Problem constants
#define T_STEPS 16384
#define HID     2048
#define IN_SZ   512
#define OUT_SZ  512
#define WH_LD   2560      // HID + IN_SZ
#define NBLK    128       // CTAs in recurrence kernel
#define RPB     16        // rows of h per CTA (NBLK*RPB == HID)

// ---------------------------------------------------------------------------
// Scratch (device globals — no allocation allowed)
// ---------------------------------------------------------------------------
__device__ float g_pre[(size_t)T_STEPS * HID];   // 128 MB: Wx@x_t + bh
__device__ float g_H  [(size_t)T_STEPS * HID];   // 128 MB: h_t for output GEMM
__device__ float g_h[2][HID];                    // double-buffered h broadcast
__device__ int   g_flag[NBLK];                   // per-CTA epoch flags

// ---------------------------------------------------------------------------
// PTX helpers
// ---------------------------------------------------------------------------
__device__ __forceinline__ int ld_acq(const int* p) {
    int v;
    asm volatile("ld.acquire.gpu.global.s32 %0,[%1];" : "=r"(v) : "l"(p));
    return v;
}
__device__ __forceinline__ float4 ldcg4(const float4* p) {
    float4 v;
    asm volatile("ld.global.cg.v4.f32 {%0,%1,%2,%3},[%4];"
                 : "=f"(v.x), "=f"(v.y), "=f"(v.z), "=f"(v.w) : "l"(p));
    return v;
}
__device__ __forceinline__ void stcg1(float* p, float a) {
    asm volatile("st.global.cg.f32 [%0],%1;" :: "l"(p), "f"(a) : "memory");
}
__device__ __forceinline__ void st_relaxed(int* p, int v) {
    asm volatile("st.relaxed.gpu.global.s32 [%0],%1;" :: "l"(p), "r"(v) : "memory");
}
__device__ __forceinline__ void fence_gpu() {
    asm volatile("fence.acq_rel.gpu;" ::: "memory");
}
// packed fp32x2 ops (Blackwell); 64-bit register pairs
__device__ __forceinline__ unsigned long long pack2(float lo, float hi) {
    unsigned long long r;
    asm("mov.b64 %0,{%1,%2};" : "=l"(r) : "f"(lo), "f"(hi));
    return r;
}
__device__ __forceinline__ void unpack2(unsigned long long v, float& lo, float& hi) {
    asm("mov.b64 {%0,%1},%2;" : "=f"(lo), "=f"(hi) : "l"(v));
}
__device__ __forceinline__ unsigned long long mul2(unsigned long long a, unsigned long long b) {
    unsigned long long d;
    asm("mul.rn.f32x2 %0,%1,%2;" : "=l"(d) : "l"(a), "l"(b));
    return d;
}
__device__ __forceinline__ unsigned long long fma2(unsigned long long a, unsigned long long b,
                                                   unsigned long long c) {
    unsigned long long d;
    asm("fma.rn.f32x2 %0,%1,%2,%3;" : "=l"(d) : "l"(a), "l"(b), "l"(c));
    return d;
}

// ---------------------------------------------------------------------------
// Init: seed h_0, zero flags. Runs every launch (graph replay safe).
// ---------------------------------------------------------------------------
__global__ void init_kernel(const float* __restrict__ h0) {
    int i = blockIdx.x * blockDim.x + threadIdx.x;
    if (i < HID) {
        g_h[0][i] = h0[i];
        g_h[1][i] = 0.f;
    }
    if (i < NBLK) g_flag[i] = 0;
}

// ---------------------------------------------------------------------------
// Generic fp32 SGEMM with bias:  C[m][n] = bias[n] + sum_k A[m][k]*B[n][k]
// BM=BN=128, BK=8, 256 threads, 8x8 per thread.
// ---------------------------------------------------------------------------
__global__ __launch_bounds__(256) void sgemm_bias(
    const float* __restrict__ A, int lda,
    const float* __restrict__ B, int ldb,
    const float* __restrict__ bias,
    float* __restrict__ C, int ldc, int K)
{
    __shared__ float As[8][128];
    __shared__ float Bs[8][128];
    const int tid  = threadIdx.x;
    const size_t m0 = (size_t)blockIdx.y * 128;
    const int n0   = blockIdx.x * 128;
    const int lrow = tid >> 1;
    const int lc4  = (tid & 1) * 4;
    const int tx   = tid & 15, ty = tid >> 4;

    const float* Ap = A + (m0 + lrow) * (size_t)lda + lc4;
    const float* Bp = B + ((size_t)(n0 + lrow)) * (size_t)ldb + lc4;

    float acc[8][8];
    #pragma unroll
    for (int i = 0; i < 8; i++)
        #pragma unroll
        for (int j = 0; j < 8; j++) acc[i][j] = 0.f;

    for (int k0 = 0; k0 < K; k0 += 8) {
        float4 a4 = *(const float4*)(Ap + k0);
        float4 b4 = *(const float4*)(Bp + k0);
        __syncthreads();
        As[lc4+0][lrow] = a4.x; As[lc4+1][lrow] = a4.y;
        As[lc4+2][lrow] = a4.z; As[lc4+3][lrow] = a4.w;
        Bs[lc4+0][lrow] = b4.x; Bs[lc4+1][lrow] = b4.y;
        Bs[lc4+2][lrow] = b4.z; Bs[lc4+3][lrow] = b4.w;
        __syncthreads();
        #pragma unroll
        for (int kk = 0; kk < 8; kk++) {
            float ar[8], br[8];
            *(float4*)&ar[0] = *(const float4*)&As[kk][ty*8];
            *(float4*)&ar[4] = *(const float4*)&As[kk][ty*8+4];
            *(float4*)&br[0] = *(const float4*)&Bs[kk][tx*8];
            *(float4*)&br[4] = *(const float4*)&Bs[kk][tx*8+4];
            #pragma unroll
            for (int i = 0; i < 8; i++)
                #pragma unroll
                for (int j = 0; j < 8; j++)
                    acc[i][j] = fmaf(ar[i], br[j], acc[i][j]);
        }
    }

    float bv[8];
    *(float4*)&bv[0] = *(const float4*)&bias[n0 + tx*8];
    *(float4*)&bv[4] = *(const float4*)&bias[n0 + tx*8 + 4];
    #pragma unroll
    for (int i = 0; i < 8; i++) {
        size_t crow = m0 + ty*8 + i;
        float4 o0 = make_float4(acc[i][0]+bv[0], acc[i][1]+bv[1],
                                acc[i][2]+bv[2], acc[i][3]+bv[3]);
        float4 o1 = make_float4(acc[i][4]+bv[4], acc[i][5]+bv[5],
                                acc[i][6]+bv[6], acc[i][7]+bv[7]);
        *(float4*)&C[crow * (size_t)ldc + n0 + tx*8]     = o0;
        *(float4*)&C[crow * (size_t)ldc + n0 + tx*8 + 4] = o1;
    }
}

// ---------------------------------------------------------------------------
// Persistent recurrence kernel. 128 CTAs x 512 threads, all co-resident.
// CTA b owns h-rows [16b,16b+16). Whh slice in registers, packed as f32x2
// row-pairs: wp[p][c] = (Wh[row0+2p][col c], Wh[row0+2p+1][col c]).
// Warp w covers columns [128w,128w+128); lane l covers c0=128w+4l..c0+3.
// Sync: per-CTA epoch flags; warp w polls only its 8 producer CTAs.
// ---------------------------------------------------------------------------
__global__ __launch_bounds__(512, 1) void rnn_kernel(const float* __restrict__ Wh)
{
    const int tid  = threadIdx.x;
    const int w    = tid >> 5;
    const int l    = tid & 31;
    const int row0 = blockIdx.x * RPB;
    const int c0   = w * 128 + l * 4;

    // Load + pack this lane's Whh slice (hidden cols 512..2559)
    unsigned long long wp[8][4];
    #pragma unroll
    for (int p = 0; p < 8; p++) {
        float4 a = *(const float4*)&Wh[(size_t)(row0 + 2*p    ) * WH_LD + IN_SZ + c0];
        float4 b = *(const float4*)&Wh[(size_t)(row0 + 2*p + 1) * WH_LD + IN_SZ + c0];
        wp[p][0] = pack2(a.x, b.x);
        wp[p][1] = pack2(a.y, b.y);
        wp[p][2] = pack2(a.z, b.z);
        wp[p][3] = pack2(a.w, b.w);
    }

    __shared__ float sred[2][16 * RPB];   // [parity][warp*16 + row]

    const int* myflags = &g_flag[w * 8];  // 8 producer CTAs for my columns
    const int fidx = (l < 8) ? l : 0;

    for (int t = 1; t <= T_STEPS; t++) {
        // Prefetch pre-activation for my rows (independent of h)
        float pre = 0.f;
        if (tid < RPB)
            pre = g_pre[(size_t)(t - 1) * HID + row0 + tid];

        // ---- wait for my 8 producer CTAs to publish h_{t-1} ----
        const int need = t - 1;
        bool ok = (l >= 8);
        while (true) {
            if (!ok) ok = (ld_acq(&myflags[fidx]) >= need);
            if (__ballot_sync(0xffffffffu, ok) == 0xffffffffu) break;
        }

        // ---- load my 4 h columns (L2) ----
        float4 hv = ldcg4((const float4*)&g_h[(t - 1) & 1][c0]);
        const unsigned long long h0 = pack2(hv.x, hv.x);
        const unsigned long long h1 = pack2(hv.y, hv.y);
        const unsigned long long h2 = pack2(hv.z, hv.z);
        const unsigned long long h3 = pack2(hv.w, hv.w);

        // ---- packed partial dot products: 16 rows (8 pairs) x 4 cols ----
        float v[RPB];
        #pragma unroll
        for (int p = 0; p < 8; p++) {
            unsigned long long acc = mul2(wp[p][0], h0);
            acc = fma2(wp[p][1], h1, acc);
            acc = fma2(wp[p][2], h2, acc);
            acc = fma2(wp[p][3], h3, acc);
            unpack2(acc, v[2*p], v[2*p + 1]);
        }

        // ---- packed butterfly: reduce 16 values across 32 lanes ----
        {
            const bool hi = (l & 16);
            #pragma unroll
            for (int i = 0; i < 8; i++) {
                float keep = hi ? v[i+8] : v[i];
                float send = hi ? v[i]   : v[i+8];
                v[i] = keep + __shfl_xor_sync(0xffffffffu, send, 16);
            }
        }
        {
            const bool hi = (l & 8);
            #pragma unroll
            for (int i = 0; i < 4; i++) {
                float keep = hi ? v[i+4] : v[i];
                float send = hi ? v[i]   : v[i+4];
                v[i] = keep + __shfl_xor_sync(0xffffffffu, send, 8);
            }
        }
        {
            const bool hi = (l & 4);
            #pragma unroll
            for (int i = 0; i < 2; i++) {
                float keep = hi ? v[i+2] : v[i];
                float send = hi ? v[i]   : v[i+2];
                v[i] = keep + __shfl_xor_sync(0xffffffffu, send, 4);
            }
        }
        {
            const bool hi = (l & 2);
            float keep = hi ? v[1] : v[0];
            float send = hi ? v[0] : v[1];
            v[0] = keep + __shfl_xor_sync(0xffffffffu, send, 2);
        }
        v[0] += __shfl_xor_sync(0xffffffffu, v[0], 1);
        // even lane L holds stripe-sum of row (L>>1)&15

        const int par = t & 1;
        if (!(l & 1))
            sred[par][(w << 4) | ((l >> 1) & 15)] = v[0];   // [warp][row]: conflict-free
        __syncthreads();

        // ---- final cross-warp reduce + tanh + publish (warp 0, lanes 0..15)
        if (tid < RPB) {
            float s = pre;
            #pragma unroll
            for (int ww = 0; ww < 16; ww++)
                s += sred[par][(ww << 4) | tid];
            float h = tanhf(s);
            g_H[(size_t)(t - 1) * HID + row0 + tid] = h;
            stcg1(&g_h[par][row0 + tid], h);
            fence_gpu();                       // order my h store before flag bump
            __syncwarp(0x0000ffffu);
            if (tid == 0)
                st_relaxed(&g_flag[blockIdx.x], t);
        }
        // sred parity double-buffering removes the need for a trailing barrier.
    }
}

// ---------------------------------------------------------------------------
// Launch
// ---------------------------------------------------------------------------
extern "C" void kernel_launch(void* const* d_in, const int* in_sizes, int n_in,
                              void* d_out, int out_size)
{
    const float* x   = (const float*)d_in[0];  // [16384, 512]
    const float* h0  = (const float*)d_in[1];  // [2048]
    const float* Wh  = (const float*)d_in[2];  // [2048, 2560]
    const float* bh  = (const float*)d_in[3];  // [2048]
    const float* Wo  = (const float*)d_in[4];  // [512, 2048]
    const float* bo  = (const float*)d_in[5];  // [512]
    float* out = (float*)d_out;                // [16384, 512]

    float* pre = nullptr;
    float* H   = nullptr;
    cudaGetSymbolAddress((void**)&pre, g_pre);
    cudaGetSymbolAddress((void**)&H,   g_H);

    // Reset flags + seed h_0 (every launch — graph replay safe)
    init_kernel<<<(HID + 255) / 256, 256>>>(h0);

    // PRE = X @ Wx^T + bh   (Wx = Wh[:, :512], row stride 2560)
    sgemm_bias<<<dim3(HID / 128, T_STEPS / 128), 256>>>(
        x, IN_SZ, Wh, WH_LD, bh, pre, HID, IN_SZ);

    // Sequential recurrence (persistent, flag-synced)
    rnn_kernel<<<NBLK, 512>>>(Wh);

    // OUT = H @ Wo^T + bo
    sgemm_bias<<<dim3(OUT_SZ / 128, T_STEPS / 128), 256>>>(
        H, HID, Wo, HID, bo, out, OUT_SZ, HID);
}

// round 4
// speedup vs baseline: 4.3213x; 4.3213x over previous
#include <cuda_runtime.h>
#include <cstdint>

// Problem constants
#define T_STEPS 16384
#define HID     2048
#define IN_SZ   512
#define OUT_SZ  512
#define WH_LD   2560      // HID + IN_SZ
#define NBLK    128       // CTAs in recurrence kernel
#define RPB     16        // rows of h per CTA (NBLK*RPB == HID)

// ---------------------------------------------------------------------------
// Scratch (device globals — no allocation allowed)
// ---------------------------------------------------------------------------
__device__ float g_pre[(size_t)T_STEPS * HID];   // 128 MB: Wx@x_t + bh
__device__ float g_H  [(size_t)T_STEPS * HID];   // 128 MB: h_t for output GEMM
__device__ float g_h[2][HID];                    // double-buffered h broadcast
__device__ int   g_count;                        // global epoch counter

// ---------------------------------------------------------------------------
// PTX helpers
// ---------------------------------------------------------------------------
__device__ __forceinline__ int ld_acq(const int* p) {
    int v;
    asm volatile("ld.acquire.gpu.global.s32 %0,[%1];" : "=r"(v) : "l"(p));
    return v;
}
__device__ __forceinline__ float4 ldcg4(const float4* p) {
    float4 v;
    asm volatile("ld.global.cg.v4.f32 {%0,%1,%2,%3},[%4];"
                 : "=f"(v.x), "=f"(v.y), "=f"(v.z), "=f"(v.w) : "l"(p));
    return v;
}
__device__ __forceinline__ void stcg1(float* p, float a) {
    asm volatile("st.global.cg.f32 [%0],%1;" :: "l"(p), "f"(a) : "memory");
}
__device__ __forceinline__ void red_release_add(int* p, int v) {
    asm volatile("red.release.gpu.global.add.s32 [%0],%1;" :: "l"(p), "r"(v) : "memory");
}
// packed fp32x2 ops (Blackwell); 64-bit register pairs
__device__ __forceinline__ unsigned long long pack2(float lo, float hi) {
    unsigned long long r;
    asm("mov.b64 %0,{%1,%2};" : "=l"(r) : "f"(lo), "f"(hi));
    return r;
}
__device__ __forceinline__ void unpack2(unsigned long long v, float& lo, float& hi) {
    asm("mov.b64 {%0,%1},%2;" : "=f"(lo), "=f"(hi) : "l"(v));
}
__device__ __forceinline__ unsigned long long mul2(unsigned long long a, unsigned long long b) {
    unsigned long long d;
    asm("mul.rn.f32x2 %0,%1,%2;" : "=l"(d) : "l"(a), "l"(b));
    return d;
}
__device__ __forceinline__ unsigned long long fma2(unsigned long long a, unsigned long long b,
                                                   unsigned long long c) {
    unsigned long long d;
    asm("fma.rn.f32x2 %0,%1,%2,%3;" : "=l"(d) : "l"(a), "l"(b), "l"(c));
    return d;
}

// ---------------------------------------------------------------------------
// Init: seed h_0, zero counter. Runs every launch (graph replay safe).
// ---------------------------------------------------------------------------
__global__ void init_kernel(const float* __restrict__ h0) {
    int i = blockIdx.x * blockDim.x + threadIdx.x;
    if (i < HID) {
        g_h[0][i] = h0[i];
        g_h[1][i] = 0.f;
    }
    if (i == 0) g_count = 0;
}

// ---------------------------------------------------------------------------
// Generic fp32 SGEMM with bias:  C[m][n] = bias[n] + sum_k A[m][k]*B[n][k]
// BM=BN=128, BK=8, 256 threads, 8x8 per thread.
// ---------------------------------------------------------------------------
__global__ __launch_bounds__(256) void sgemm_bias(
    const float* __restrict__ A, int lda,
    const float* __restrict__ B, int ldb,
    const float* __restrict__ bias,
    float* __restrict__ C, int ldc, int K)
{
    __shared__ float As[8][128];
    __shared__ float Bs[8][128];
    const int tid  = threadIdx.x;
    const size_t m0 = (size_t)blockIdx.y * 128;
    const int n0   = blockIdx.x * 128;
    const int lrow = tid >> 1;
    const int lc4  = (tid & 1) * 4;
    const int tx   = tid & 15, ty = tid >> 4;

    const float* Ap = A + (m0 + lrow) * (size_t)lda + lc4;
    const float* Bp = B + ((size_t)(n0 + lrow)) * (size_t)ldb + lc4;

    float acc[8][8];
    #pragma unroll
    for (int i = 0; i < 8; i++)
        #pragma unroll
        for (int j = 0; j < 8; j++) acc[i][j] = 0.f;

    for (int k0 = 0; k0 < K; k0 += 8) {
        float4 a4 = *(const float4*)(Ap + k0);
        float4 b4 = *(const float4*)(Bp + k0);
        __syncthreads();
        As[lc4+0][lrow] = a4.x; As[lc4+1][lrow] = a4.y;
        As[lc4+2][lrow] = a4.z; As[lc4+3][lrow] = a4.w;
        Bs[lc4+0][lrow] = b4.x; Bs[lc4+1][lrow] = b4.y;
        Bs[lc4+2][lrow] = b4.z; Bs[lc4+3][lrow] = b4.w;
        __syncthreads();
        #pragma unroll
        for (int kk = 0; kk < 8; kk++) {
            float ar[8], br[8];
            *(float4*)&ar[0] = *(const float4*)&As[kk][ty*8];
            *(float4*)&ar[4] = *(const float4*)&As[kk][ty*8+4];
            *(float4*)&br[0] = *(const float4*)&Bs[kk][tx*8];
            *(float4*)&br[4] = *(const float4*)&Bs[kk][tx*8+4];
            #pragma unroll
            for (int i = 0; i < 8; i++)
                #pragma unroll
                for (int j = 0; j < 8; j++)
                    acc[i][j] = fmaf(ar[i], br[j], acc[i][j]);
        }
    }

    float bv[8];
    *(float4*)&bv[0] = *(const float4*)&bias[n0 + tx*8];
    *(float4*)&bv[4] = *(const float4*)&bias[n0 + tx*8 + 4];
    #pragma unroll
    for (int i = 0; i < 8; i++) {
        size_t crow = m0 + ty*8 + i;
        float4 o0 = make_float4(acc[i][0]+bv[0], acc[i][1]+bv[1],
                                acc[i][2]+bv[2], acc[i][3]+bv[3]);
        float4 o1 = make_float4(acc[i][4]+bv[4], acc[i][5]+bv[5],
                                acc[i][6]+bv[6], acc[i][7]+bv[7]);
        *(float4*)&C[crow * (size_t)ldc + n0 + tx*8]     = o0;
        *(float4*)&C[crow * (size_t)ldc + n0 + tx*8 + 4] = o1;
    }
}

// ---------------------------------------------------------------------------
// Persistent recurrence kernel. 128 CTAs x 512 threads, all co-resident.
// CTA b owns h-rows [16b,16b+16). Whh slice in registers, packed as f32x2
// row-pairs. Warp w covers columns [128w,128w+128); lane l: c0=128w+4l.
// Sync: ONE global counter. Producer: one red.release.add per CTA per step.
// Consumer: tid 0 polls with ld.acquire, __syncthreads releases the CTA.
// ---------------------------------------------------------------------------
__global__ __launch_bounds__(512, 1) void rnn_kernel(const float* __restrict__ Wh)
{
    const int tid  = threadIdx.x;
    const int w    = tid >> 5;
    const int l    = tid & 31;
    const int row0 = blockIdx.x * RPB;
    const int c0   = w * 128 + l * 4;

    // Load + pack this lane's Whh slice (hidden cols 512..2559)
    unsigned long long wp[8][4];
    #pragma unroll
    for (int p = 0; p < 8; p++) {
        float4 a = *(const float4*)&Wh[(size_t)(row0 + 2*p    ) * WH_LD + IN_SZ + c0];
        float4 b = *(const float4*)&Wh[(size_t)(row0 + 2*p + 1) * WH_LD + IN_SZ + c0];
        wp[p][0] = pack2(a.x, b.x);
        wp[p][1] = pack2(a.y, b.y);
        wp[p][2] = pack2(a.z, b.z);
        wp[p][3] = pack2(a.w, b.w);
    }

    __shared__ float sred[2][16 * RPB];   // [parity][warp*16 + row]

    for (int t = 1; t <= T_STEPS; t++) {
        // Prefetch pre-activation for my rows (independent of h)
        float pre = 0.f;
        if (tid < RPB)
            pre = g_pre[(size_t)(t - 1) * HID + row0 + tid];

        // ---- wait for all 128 CTAs to have published h_{t-1} ----
        const int target = NBLK * (t - 1);
        if (tid == 0) {
            if (ld_acq(&g_count) < target) {
                while (true) {
                    __nanosleep(16);
                    if (ld_acq(&g_count) >= target) break;
                }
            }
        }
        __syncthreads();

        // ---- load my 4 h columns (L2) ----
        float4 hv = ldcg4((const float4*)&g_h[(t - 1) & 1][c0]);
        const unsigned long long h0 = pack2(hv.x, hv.x);
        const unsigned long long h1 = pack2(hv.y, hv.y);
        const unsigned long long h2 = pack2(hv.z, hv.z);
        const unsigned long long h3 = pack2(hv.w, hv.w);

        // ---- packed partial dot products: 16 rows (8 pairs) x 4 cols ----
        float v[RPB];
        #pragma unroll
        for (int p = 0; p < 8; p++) {
            unsigned long long acc = mul2(wp[p][0], h0);
            acc = fma2(wp[p][1], h1, acc);
            acc = fma2(wp[p][2], h2, acc);
            acc = fma2(wp[p][3], h3, acc);
            unpack2(acc, v[2*p], v[2*p + 1]);
        }

        // ---- packed butterfly: reduce 16 values across 32 lanes ----
        {
            const bool hi = (l & 16);
            #pragma unroll
            for (int i = 0; i < 8; i++) {
                float keep = hi ? v[i+8] : v[i];
                float send = hi ? v[i]   : v[i+8];
                v[i] = keep + __shfl_xor_sync(0xffffffffu, send, 16);
            }
        }
        {
            const bool hi = (l & 8);
            #pragma unroll
            for (int i = 0; i < 4; i++) {
                float keep = hi ? v[i+4] : v[i];
                float send = hi ? v[i]   : v[i+4];
                v[i] = keep + __shfl_xor_sync(0xffffffffu, send, 8);
            }
        }
        {
            const bool hi = (l & 4);
            #pragma unroll
            for (int i = 0; i < 2; i++) {
                float keep = hi ? v[i+2] : v[i];
                float send = hi ? v[i]   : v[i+2];
                v[i] = keep + __shfl_xor_sync(0xffffffffu, send, 4);
            }
        }
        {
            const bool hi = (l & 2);
            float keep = hi ? v[1] : v[0];
            float send = hi ? v[0] : v[1];
            v[0] = keep + __shfl_xor_sync(0xffffffffu, send, 2);
        }
        v[0] += __shfl_xor_sync(0xffffffffu, v[0], 1);
        // even lane L holds stripe-sum of row (L>>1)&15

        const int par = t & 1;
        if (!(l & 1))
            sred[par][(w << 4) | ((l >> 1) & 15)] = v[0];   // [warp][row]: conflict-free
        __syncthreads();

        // ---- final cross-warp reduce + tanh + publish (warp 0, lanes 0..15)
        if (tid < RPB) {
            float s = pre;
            #pragma unroll
            for (int ww = 0; ww < 16; ww++)
                s += sred[par][(ww << 4) | tid];
            float h = tanhf(s);
            g_H[(size_t)(t - 1) * HID + row0 + tid] = h;
            stcg1(&g_h[par][row0 + tid], h);
            __syncwarp(0x0000ffffu);
            if (tid == 0)
                red_release_add(&g_count, 1);   // release: orders my h stores
        }
        // sred parity double-buffering removes the need for a trailing barrier.
    }
}

// ---------------------------------------------------------------------------
// Launch
// ---------------------------------------------------------------------------
extern "C" void kernel_launch(void* const* d_in, const int* in_sizes, int n_in,
                              void* d_out, int out_size)
{
    const float* x   = (const float*)d_in[0];  // [16384, 512]
    const float* h0  = (const float*)d_in[1];  // [2048]
    const float* Wh  = (const float*)d_in[2];  // [2048, 2560]
    const float* bh  = (const float*)d_in[3];  // [2048]
    const float* Wo  = (const float*)d_in[4];  // [512, 2048]
    const float* bo  = (const float*)d_in[5];  // [512]
    float* out = (float*)d_out;                // [16384, 512]

    float* pre = nullptr;
    float* H   = nullptr;
    cudaGetSymbolAddress((void**)&pre, g_pre);
    cudaGetSymbolAddress((void**)&H,   g_H);

    // Reset counter + seed h_0 (every launch — graph replay safe)
    init_kernel<<<(HID + 255) / 256, 256>>>(h0);

    // PRE = X @ Wx^T + bh   (Wx = Wh[:, :512], row stride 2560)
    sgemm_bias<<<dim3(HID / 128, T_STEPS / 128), 256>>>(
        x, IN_SZ, Wh, WH_LD, bh, pre, HID, IN_SZ);

    // Sequential recurrence (persistent, counter-synced)
    rnn_kernel<<<NBLK, 512>>>(Wh);

    // OUT = H @ Wo^T + bo
    sgemm_bias<<<dim3(OUT_SZ / 128, T_STEPS / 128), 256>>>(
        H, HID, Wo, HID, bo, out, OUT_SZ, HID);
}